// round 14
// baseline (speedup 1.0000x reference)
#include <cuda_runtime.h>
#include <cuda_bf16.h>

// RelativeAttention: B=2,H=8,S=512,D=64
// ROUND-13 DIAGNOSIS: all kernels were pinned at the L2 cap (~11.5 TB/s):
// K+V gather re-reads (0.5 GB each) tripled L2 traffic vs the R stream.
// Split into 3 kernels so L2 carries ~only R:
//   1) QK = Q@K^T tiled through smem (K read 32MB, not 512MB) -> g_qk scratch
//   2) scores: stream R (mask-compacted, cp.async) + precomputed QK, softmax
//   3) out = P@V tiled through smem (V read 32MB, not 512MB); masked p==0 exact
// Outputs concatenated in d_out: out [B,H,S,D] then p_attn [B,H,S,S].

#define Bc 2
#define Hc 8
#define Sc 512
#define Dc 64
#define TQ 4
#define THREADS 128
#define GRIDSZ 1024   // 2 contiguous tiles per CTA; 7 CTAs/SM -> all resident
#define CHUNK 8
#define FULLM 0xffffffffu

__device__ float g_qk[(size_t)Bc * Hc * Sc * Sc];   // 16 MB scratch (QK dense)

__device__ __forceinline__ unsigned su32(const void* p) {
    return (unsigned)__cvta_generic_to_shared(p);
}
__device__ __forceinline__ void cp_async16(unsigned sa, const void* g) {
    asm volatile("cp.async.cg.shared.global [%0], [%1], 16;" :: "r"(sa), "l"(g));
}
__device__ __forceinline__ void cp_commit() {
    asm volatile("cp.async.commit_group;" ::: "memory");
}
template<int N> __device__ __forceinline__ void cp_wait() {
    asm volatile("cp.async.wait_group %0;" :: "n"(N) : "memory");
}

// ============================================================================
// Kernel 1: QK[b,h,q,k] = sum_d Q[q,d] K[k,d].  CTA = 32 q-rows x 256 k-cols.
// K tile transposed in smem; each thread owns 8 k-cols (2 float4 groups).
// ============================================================================
__global__ __launch_bounds__(256)
void qk_kernel(const float* __restrict__ Q, const float* __restrict__ K)
{
    __shared__ float  Qt[32][65];        // [qrow][d]
    __shared__ float4 KtT[64][17];       // [d][k/4]  (68-float rows)

    const int x  = blockIdx.x;           // 0..31: qt = x>>1, khalf = x&1
    const int h  = blockIdx.y;
    const int b  = blockIdx.z;
    const long bh = (long)b * Hc + h;
    const int q0 = (x >> 1) * 32;
    const int k0 = (x & 1) * 256;
    const int tid = threadIdx.x;
    const int ql = tid >> 3;             // 0..31
    const int kq = tid & 7;              // 0..7

    for (int i = tid; i < 32 * Dc; i += 256) {
        const int r = i >> 6, d = i & 63;
        Qt[r][d] = Q[(bh * Sc + q0 + r) * Dc + d];
    }

    for (int kc = 0; kc < 4; ++kc) {
        __syncthreads();                 // prev compute done before KtT overwrite
        for (int i = tid; i < 64 * 64; i += 256) {
            const int d = i & 63, kr = i >> 6;
            ((float*)&KtT[d][0])[kr] = K[(bh * Sc + k0 + kc * 64 + kr) * Dc + d];
        }
        __syncthreads();

        float4 a0 = make_float4(0.f, 0.f, 0.f, 0.f);
        float4 a1 = make_float4(0.f, 0.f, 0.f, 0.f);
        #pragma unroll 8
        for (int dd = 0; dd < 64; ++dd) {
            const float qd = Qt[ql][dd];
            const float4 k0v = KtT[dd][kq];
            const float4 k1v = KtT[dd][kq + 8];
            a0.x += qd * k0v.x; a0.y += qd * k0v.y;
            a0.z += qd * k0v.z; a0.w += qd * k0v.w;
            a1.x += qd * k1v.x; a1.y += qd * k1v.y;
            a1.z += qd * k1v.z; a1.w += qd * k1v.w;
        }
        // lanes 0-7 cover one contiguous 128B sector per row: coalesced
        float* orow = g_qk + (bh * Sc + q0 + ql) * (long)Sc + k0 + kc * 64;
        *(float4*)(orow + kq * 4)      = a0;
        *(float4*)(orow + kq * 4 + 32) = a1;
    }
}

// ============================================================================
// Kernel 2: scores + softmax.  Round-13 R streamer, K loads deleted;
// p_sh initialized to (mask ? QK : -8e9) during compaction.
// ============================================================================
__global__ __launch_bounds__(THREADS, 7)
void scores_kernel(const float* __restrict__ Q, const float* __restrict__ R,
                   const int* __restrict__ M, float* __restrict__ p_out)
{
    __shared__ float p_sh[TQ][Sc];                     // 8 KB   per-warp slice
    __shared__ unsigned short idx_sh[TQ][Sc + 16];     // 4.1 KB per-warp slice
    __shared__ float r_buf[TQ][2][CHUNK][Dc];          // 16 KB  per-warp slice

    const int tid  = threadIdx.x;
    const int w    = tid >> 5;
    const int lane = tid & 31;
    const int rg   = lane >> 3;
    const int l8   = lane & 7;

    for (int ti = 0; ti < 2; ++ti) {
        const int t  = blockIdx.x * 2 + ti;
        const int qt = t & (Sc / TQ - 1);
        const int h  = (t >> 7) & (Hc - 1);
        const int b  = t >> 10;

        const int qrow = qt * TQ + w;
        const long bh = (long)b * Hc + h;

        const float* Qrow  = Q + (bh * Sc + (long)qrow) * Dc;
        const float* Rrow  = R + ((bh * Sc + (long)qrow) * (long)Sc) * Dc;
        const int*   Mrow  = M + (((long)b * Sc + qrow) * Sc);
        const float* QKrow = g_qk + (bh * Sc + (long)qrow) * (long)Sc;

        const float4 qa = __ldg((const float4*)Qrow + l8);
        const float4 qb = __ldg((const float4*)Qrow + l8 + 8);

        // ---- compaction + p_sh init (QK for unmasked, -8e9 for masked) ----
        int cnt = 0;
        #pragma unroll
        for (int i = 0; i < Sc / 32; ++i) {
            const int kk = i * 32 + lane;
            const bool m = (__ldg(Mrow + kk) != 0);
            const float qk = __ldg(QKrow + kk);
            const unsigned bal = __ballot_sync(FULLM, m);
            const int pos = cnt + __popc(bal & ((1u << lane) - 1u));
            if (m) idx_sh[w][pos] = (unsigned short)kk;
            cnt += __popc(bal);
            p_sh[w][kk] = m ? qk : -8.0e9f;            // *0.125 -> -1e9
        }
        __syncwarp();
        if (lane < 16) idx_sh[w][cnt + lane] = (cnt > 0) ? idx_sh[w][0] : (unsigned short)0;
        __syncwarp();

        const int nch = (cnt + CHUNK - 1) / CHUNK;

        // Self-consumed fill: lane prefetches exactly the bytes it will read.
        auto fillR = [&](int j) {
            const int s = j & 1;
            const int kk0 = (int)idx_sh[w][j * CHUNK + rg];
            const int kk1 = (int)idx_sh[w][j * CHUNK + 4 + rg];
            const float* g0 = Rrow + (long)kk0 * Dc + (l8 << 2);
            const float* g1 = Rrow + (long)kk1 * Dc + (l8 << 2);
            const unsigned s0 = su32(&r_buf[w][s][rg][l8 << 2]);
            const unsigned s1 = su32(&r_buf[w][s][4 + rg][l8 << 2]);
            cp_async16(s0,       g0);
            cp_async16(s0 + 128, g0 + 32);
            cp_async16(s1,       g1);
            cp_async16(s1 + 128, g1 + 32);
        };

        if (nch > 0) { fillR(0); cp_commit(); }

        for (int c = 0; c < nch; ++c) {
            const int s = c & 1;
            const int base = c * CHUNK;
            if (c + 1 < nch) { fillR(c + 1); cp_commit(); cp_wait<1>(); }
            else             { cp_wait<0>(); }

            const int jj0 = base + rg, jj1 = base + 4 + rg;
            const int kk0 = (int)idx_sh[w][jj0];
            const int kk1 = (int)idx_sh[w][jj1];
            const float4 ra0 = *(const float4*)&r_buf[w][s][rg][l8 << 2];
            const float4 rb0 = *(const float4*)&r_buf[w][s][rg][(l8 << 2) + 32];
            const float4 ra1 = *(const float4*)&r_buf[w][s][4 + rg][l8 << 2];
            const float4 rb1 = *(const float4*)&r_buf[w][s][4 + rg][(l8 << 2) + 32];

            float s0 = qa.x * ra0.x + qa.y * ra0.y + qa.z * ra0.z + qa.w * ra0.w
                     + qb.x * rb0.x + qb.y * rb0.y + qb.z * rb0.z + qb.w * rb0.w;
            float s1 = qa.x * ra1.x + qa.y * ra1.y + qa.z * ra1.z + qa.w * ra1.w
                     + qb.x * rb1.x + qb.y * rb1.y + qb.z * rb1.z + qb.w * rb1.w;
            s0 += __shfl_xor_sync(FULLM, s0, 4);
            s0 += __shfl_xor_sync(FULLM, s0, 2);
            s0 += __shfl_xor_sync(FULLM, s0, 1);
            s1 += __shfl_xor_sync(FULLM, s1, 4);
            s1 += __shfl_xor_sync(FULLM, s1, 2);
            s1 += __shfl_xor_sync(FULLM, s1, 1);
            if (l8 == 0 && jj0 < cnt) p_sh[w][kk0] += s0;   // QK already there
            if (l8 == 0 && jj1 < cnt) p_sh[w][kk1] += s1;
        }
        __syncwarp();

        // ---- softmax: masked entries underflow to exact 0 ----
        float vals[Sc / 32];
        float mx = -3.0e38f;
        #pragma unroll
        for (int i = 0; i < Sc / 32; ++i) {
            const float sv = p_sh[w][lane + 32 * i] * 0.125f;
            vals[i] = sv;
            mx = fmaxf(mx, sv);
        }
        #pragma unroll
        for (int o = 16; o; o >>= 1) mx = fmaxf(mx, __shfl_xor_sync(FULLM, mx, o));
        float sum = 0.f;
        #pragma unroll
        for (int i = 0; i < Sc / 32; ++i) {
            const float e = __expf(vals[i] - mx);
            vals[i] = e;
            sum += e;
        }
        #pragma unroll
        for (int o = 16; o; o >>= 1) sum += __shfl_xor_sync(FULLM, sum, o);
        const float inv = 1.0f / sum;

        float* prow2 = p_out + (bh * Sc + (long)qrow) * Sc;
        #pragma unroll
        for (int i = 0; i < Sc / 32; ++i) {
            const int kk = lane + 32 * i;
            prow2[kk] = vals[i] * inv;   // keep in L2: AV kernel reads it next
        }
    }
}

// ============================================================================
// Kernel 3: out = P @ V.  CTA = 32 q-rows, full D; V tiled through smem.
// ============================================================================
__global__ __launch_bounds__(256)
void av_kernel(const float* __restrict__ V, const float* __restrict__ P,
               float* __restrict__ out)
{
    __shared__ float  Pt[32][65];        // [qrow][k]
    __shared__ float4 Vt[64][17];        // [k][d/4]  (68-float rows)

    const int qt = blockIdx.x;           // 0..15
    const int h  = blockIdx.y;
    const int b  = blockIdx.z;
    const long bh = (long)b * Hc + h;
    const int q0 = qt * 32;
    const int tid = threadIdx.x;
    const int ql = tid >> 3;             // 0..31
    const int dq = tid & 7;              // 0..7

    float4 a0 = make_float4(0.f, 0.f, 0.f, 0.f);
    float4 a1 = make_float4(0.f, 0.f, 0.f, 0.f);

    for (int kc = 0; kc < 8; ++kc) {
        __syncthreads();
        for (int i = tid; i < 32 * 64; i += 256) {
            const int r = i >> 6, c = i & 63;
            Pt[r][c] = P[(bh * Sc + q0 + r) * (long)Sc + kc * 64 + c];
        }
        for (int i = tid; i < 64 * 64; i += 256) {
            const int d = i & 63, kr = i >> 6;
            ((float*)&Vt[kr][0])[d] = V[(bh * Sc + kc * 64 + kr) * Dc + d];
        }
        __syncthreads();

        #pragma unroll 8
        for (int kk = 0; kk < 64; ++kk) {
            const float pv = Pt[ql][kk];
            const float4 v0 = Vt[kk][dq];
            const float4 v1 = Vt[kk][dq + 8];
            a0.x += pv * v0.x; a0.y += pv * v0.y;
            a0.z += pv * v0.z; a0.w += pv * v0.w;
            a1.x += pv * v1.x; a1.y += pv * v1.y;
            a1.z += pv * v1.z; a1.w += pv * v1.w;
        }
    }
    float* orow = out + (bh * Sc + q0 + ql) * Dc;
    *(float4*)(orow + dq * 4)      = a0;
    *(float4*)(orow + dq * 4 + 32) = a1;
}

extern "C" void kernel_launch(void* const* d_in, const int* in_sizes, int n_in,
                              void* d_out, int out_size)
{
    const float* Q = (const float*)d_in[0];
    const float* K = (const float*)d_in[1];
    const float* V = (const float*)d_in[2];
    const float* R = (const float*)d_in[3];
    const int*   M = (const int*)d_in[4];

    float* out   = (float*)d_out;                    // [B,H,S,D]
    float* p_out = out + (long)Bc * Hc * Sc * Dc;    // [B,H,S,S] appended

    qk_kernel<<<dim3(32, Hc, Bc), 256>>>(Q, K);
    scores_kernel<<<GRIDSZ, THREADS>>>(Q, R, M, p_out);
    av_kernel<<<dim3(16, Hc, Bc), 256>>>(V, p_out, out);
}

// round 17
// speedup vs baseline: 1.3374x; 1.3374x over previous
#include <cuda_runtime.h>
#include <cuda_bf16.h>

// RelativeAttention: B=2,H=8,S=512,D=64
// Split: (1) QK GEMM (register-blocked, f32x2 FMA) -> g_qk scratch;
//        (2) fused scores+softmax+AV: mask-compacted R stream (cp.async,
//            self-consumed), QK added from scratch, gathered AV.
// Round-16 fix: smem tile row stride 65 -> 68 floats (float4 alignment; the
// 65-stride made &Qs[dd][x] misaligned for odd dd -> HW trap).
// Outputs concatenated in d_out: out [B,H,S,D] then p_attn [B,H,S,S].

#define Bc 2
#define Hc 8
#define Sc 512
#define Dc 64
#define TQ 4
#define THREADS 128
#define GRIDSZ 1024   // 2 contiguous tiles per CTA; 8 CTAs/SM -> all resident
#define CHUNK 8
#define FULLM 0xffffffffu

__device__ float g_qk[(size_t)Bc * Hc * Sc * Sc];   // 16 MB scratch (QK dense)

__device__ __forceinline__ unsigned su32(const void* p) {
    return (unsigned)__cvta_generic_to_shared(p);
}
__device__ __forceinline__ void cp_async16(unsigned sa, const void* g) {
    asm volatile("cp.async.cg.shared.global [%0], [%1], 16;" :: "r"(sa), "l"(g));
}
__device__ __forceinline__ void cp_commit() {
    asm volatile("cp.async.commit_group;" ::: "memory");
}
template<int N> __device__ __forceinline__ void cp_wait() {
    asm volatile("cp.async.wait_group %0;" :: "n"(N) : "memory");
}
__device__ __forceinline__ unsigned long long pk2(float a, float b) {
    unsigned long long r;
    asm("mov.b64 %0, {%1, %2};" : "=l"(r) : "f"(a), "f"(b));
    return r;
}
__device__ __forceinline__ void fma2(unsigned long long& d,
                                     unsigned long long a, unsigned long long b) {
    asm("fma.rn.f32x2 %0, %1, %2, %0;" : "+l"(d) : "l"(a), "l"(b));
}
__device__ __forceinline__ float2 upk2(unsigned long long v) {
    float2 r;
    asm("mov.b64 {%0, %1}, %2;" : "=f"(r.x), "=f"(r.y) : "l"(v));
    return r;
}

// ============================================================================
// Kernel 1: QK[b,h,q,k] = sum_d Q[q,d] K[k,d].
// CTA = 64q x 64k tile; 256 threads; thread = 4x4 outputs; f32x2 accumulate.
// Row stride 68 floats (272 B): every float4 within a row is 16B-aligned.
// ============================================================================
#define QS_STRIDE 68

__global__ __launch_bounds__(256)
void qk_kernel(const float* __restrict__ Q, const float* __restrict__ K)
{
    __shared__ float Qs[Dc][QS_STRIDE];  // [d][qrow]  17 KB
    __shared__ float Ks[Dc][QS_STRIDE];  // [d][krow]  17 KB

    const int tile = blockIdx.x;         // 0..63 (8x8 tiles)
    const int h = blockIdx.y, b = blockIdx.z;
    const long bh = (long)b * Hc + h;
    const int q0 = (tile >> 3) * 64;
    const int k0 = (tile & 7) * 64;
    const int tid = threadIdx.x;
    const int tx = tid & 15, ty = tid >> 4;

    #pragma unroll
    for (int i = tid; i < 1024; i += 256) {          // 1024 float4 per tensor
        const int r = i >> 4, dg = i & 15;
        const float4 v = *(const float4*)(Q + (bh * Sc + q0 + r) * Dc + dg * 4);
        Qs[dg * 4 + 0][r] = v.x; Qs[dg * 4 + 1][r] = v.y;
        Qs[dg * 4 + 2][r] = v.z; Qs[dg * 4 + 3][r] = v.w;
        const float4 u = *(const float4*)(K + (bh * Sc + k0 + r) * Dc + dg * 4);
        Ks[dg * 4 + 0][r] = u.x; Ks[dg * 4 + 1][r] = u.y;
        Ks[dg * 4 + 2][r] = u.z; Ks[dg * 4 + 3][r] = u.w;
    }
    __syncthreads();

    unsigned long long acc[4][2];
    #pragma unroll
    for (int i = 0; i < 4; ++i) { acc[i][0] = 0ull; acc[i][1] = 0ull; }

    #pragma unroll 4
    for (int dd = 0; dd < Dc; ++dd) {
        const float4 qv = *(const float4*)&Qs[dd][ty * 4];
        const float4 kv = *(const float4*)&Ks[dd][tx * 4];
        const unsigned long long k01 = pk2(kv.x, kv.y);
        const unsigned long long k23 = pk2(kv.z, kv.w);
        const float qr[4] = {qv.x, qv.y, qv.z, qv.w};
        #pragma unroll
        for (int i = 0; i < 4; ++i) {
            const unsigned long long qq = pk2(qr[i], qr[i]);
            fma2(acc[i][0], qq, k01);
            fma2(acc[i][1], qq, k23);
        }
    }

    #pragma unroll
    for (int i = 0; i < 4; ++i) {
        const float2 lo = upk2(acc[i][0]);
        const float2 hi = upk2(acc[i][1]);
        float4 o; o.x = lo.x; o.y = lo.y; o.z = hi.x; o.w = hi.y;
        *(float4*)(g_qk + (bh * Sc + q0 + ty * 4 + i) * (long)Sc + k0 + tx * 4) = o;
    }
}

// ============================================================================
// Kernel 2: fused scores + softmax + AV.  Warp-autonomous, no K loads in the
// stream (QK precomputed).  R: self-consumed 2-stage cp.async ring.
// ============================================================================
__global__ __launch_bounds__(THREADS, 8)
void scores_av_kernel(const float* __restrict__ Q, const float* __restrict__ V,
                      const float* __restrict__ R, const int* __restrict__ M,
                      float* __restrict__ out, float* __restrict__ p_out)
{
    __shared__ float p_sh[TQ][Sc];                     // 8 KB   per-warp slice
    __shared__ unsigned short idx_sh[TQ][Sc + 16];     // 4.1 KB per-warp slice
    __shared__ float r_buf[TQ][2][CHUNK][Dc];          // 16 KB  per-warp slice

    const int tid  = threadIdx.x;
    const int w    = tid >> 5;
    const int lane = tid & 31;
    const int rg   = lane >> 3;
    const int l8   = lane & 7;

    for (int ti = 0; ti < 2; ++ti) {
        const int t  = blockIdx.x * 2 + ti;
        const int qt = t & (Sc / TQ - 1);
        const int h  = (t >> 7) & (Hc - 1);
        const int b  = t >> 10;

        const int qrow = qt * TQ + w;
        const long bh = (long)b * Hc + h;

        const float* Vb    = V + bh * Sc * Dc;
        const float* Qrow  = Q + (bh * Sc + (long)qrow) * Dc;
        const float* Rrow  = R + ((bh * Sc + (long)qrow) * (long)Sc) * Dc;
        const int*   Mrow  = M + (((long)b * Sc + qrow) * Sc);
        const float* QKrow = g_qk + (bh * Sc + (long)qrow) * (long)Sc;

        const float4 qa = __ldg((const float4*)Qrow + l8);
        const float4 qb = __ldg((const float4*)Qrow + l8 + 8);

        // ---- compaction + p_sh init (QK for unmasked, -8e9 for masked) ----
        int cnt = 0;
        #pragma unroll
        for (int i = 0; i < Sc / 32; ++i) {
            const int kk = i * 32 + lane;
            const bool m = (__ldg(Mrow + kk) != 0);
            const float qk = __ldg(QKrow + kk);
            const unsigned bal = __ballot_sync(FULLM, m);
            const int pos = cnt + __popc(bal & ((1u << lane) - 1u));
            if (m) idx_sh[w][pos] = (unsigned short)kk;
            cnt += __popc(bal);
            p_sh[w][kk] = m ? qk : -8.0e9f;            // *0.125 -> -1e9
        }
        __syncwarp();
        if (lane < 16) idx_sh[w][cnt + lane] = (cnt > 0) ? idx_sh[w][0] : (unsigned short)0;
        __syncwarp();

        const int nch = (cnt + CHUNK - 1) / CHUNK;

        // Self-consumed fill: lane prefetches exactly the bytes it will read.
        auto fillR = [&](int j) {
            const int s = j & 1;
            const int kk0 = (int)idx_sh[w][j * CHUNK + rg];
            const int kk1 = (int)idx_sh[w][j * CHUNK + 4 + rg];
            const float* g0 = Rrow + (long)kk0 * Dc + (l8 << 2);
            const float* g1 = Rrow + (long)kk1 * Dc + (l8 << 2);
            const unsigned s0 = su32(&r_buf[w][s][rg][l8 << 2]);
            const unsigned s1 = su32(&r_buf[w][s][4 + rg][l8 << 2]);
            cp_async16(s0,       g0);
            cp_async16(s0 + 128, g0 + 32);
            cp_async16(s1,       g1);
            cp_async16(s1 + 128, g1 + 32);
        };

        if (nch > 0) { fillR(0); cp_commit(); }

        for (int c = 0; c < nch; ++c) {
            const int s = c & 1;
            const int base = c * CHUNK;
            if (c + 1 < nch) { fillR(c + 1); cp_commit(); cp_wait<1>(); }
            else             { cp_wait<0>(); }

            const int jj0 = base + rg, jj1 = base + 4 + rg;
            const int kk0 = (int)idx_sh[w][jj0];
            const int kk1 = (int)idx_sh[w][jj1];
            const float4 ra0 = *(const float4*)&r_buf[w][s][rg][l8 << 2];
            const float4 rb0 = *(const float4*)&r_buf[w][s][rg][(l8 << 2) + 32];
            const float4 ra1 = *(const float4*)&r_buf[w][s][4 + rg][l8 << 2];
            const float4 rb1 = *(const float4*)&r_buf[w][s][4 + rg][(l8 << 2) + 32];

            float s0 = qa.x * ra0.x + qa.y * ra0.y + qa.z * ra0.z + qa.w * ra0.w
                     + qb.x * rb0.x + qb.y * rb0.y + qb.z * rb0.z + qb.w * rb0.w;
            float s1 = qa.x * ra1.x + qa.y * ra1.y + qa.z * ra1.z + qa.w * ra1.w
                     + qb.x * rb1.x + qb.y * rb1.y + qb.z * rb1.z + qb.w * rb1.w;
            s0 += __shfl_xor_sync(FULLM, s0, 4);
            s0 += __shfl_xor_sync(FULLM, s0, 2);
            s0 += __shfl_xor_sync(FULLM, s0, 1);
            s1 += __shfl_xor_sync(FULLM, s1, 4);
            s1 += __shfl_xor_sync(FULLM, s1, 2);
            s1 += __shfl_xor_sync(FULLM, s1, 1);
            if (l8 == 0 && jj0 < cnt) p_sh[w][kk0] += s0;   // QK already there
            if (l8 == 0 && jj1 < cnt) p_sh[w][kk1] += s1;
        }
        __syncwarp();

        // ---- softmax: masked entries underflow to exact 0 ----
        float vals[Sc / 32];
        float mx = -3.0e38f;
        #pragma unroll
        for (int i = 0; i < Sc / 32; ++i) {
            const float sv = p_sh[w][lane + 32 * i] * 0.125f;
            vals[i] = sv;
            mx = fmaxf(mx, sv);
        }
        #pragma unroll
        for (int o = 16; o; o >>= 1) mx = fmaxf(mx, __shfl_xor_sync(FULLM, mx, o));
        float sum = 0.f;
        #pragma unroll
        for (int i = 0; i < Sc / 32; ++i) {
            const float e = __expf(vals[i] - mx);
            vals[i] = e;
            sum += e;
        }
        #pragma unroll
        for (int o = 16; o; o >>= 1) sum += __shfl_xor_sync(FULLM, sum, o);
        const float inv = 1.0f / sum;

        float* prow2 = p_out + (bh * Sc + (long)qrow) * Sc;
        #pragma unroll
        for (int i = 0; i < Sc / 32; ++i) {
            const int kk = lane + 32 * i;
            const float p = vals[i] * inv;            // exact 0 if masked
            p_sh[w][kk] = p;
            __stcs(prow2 + kk, p);
        }
        __syncwarp();

        // ---- AV over compacted indices ----
        float2 acc0 = make_float2(0.f, 0.f), acc1 = make_float2(0.f, 0.f);
        const int cnt4 = (cnt + 3) & ~3;
        #pragma unroll 2
        for (int j = 0; j < cnt4; j += 4) {
            const int k0 = (int)idx_sh[w][j];
            const int k1 = (int)idx_sh[w][j + 1];
            const int k2 = (int)idx_sh[w][j + 2];
            const int k3 = (int)idx_sh[w][j + 3];
            const float2 v0 = __ldg((const float2*)(Vb + (long)k0 * Dc) + lane);
            const float2 v1 = __ldg((const float2*)(Vb + (long)k1 * Dc) + lane);
            const float2 v2 = __ldg((const float2*)(Vb + (long)k2 * Dc) + lane);
            const float2 v3 = __ldg((const float2*)(Vb + (long)k3 * Dc) + lane);
            const float p0 = p_sh[w][k0];
            const float p1 = (j + 1 < cnt) ? p_sh[w][k1] : 0.f;
            const float p2 = (j + 2 < cnt) ? p_sh[w][k2] : 0.f;
            const float p3 = (j + 3 < cnt) ? p_sh[w][k3] : 0.f;
            acc0.x += p0 * v0.x; acc0.y += p0 * v0.y;
            acc1.x += p1 * v1.x; acc1.y += p1 * v1.y;
            acc0.x += p2 * v2.x; acc0.y += p2 * v2.y;
            acc1.x += p3 * v3.x; acc1.y += p3 * v3.y;
        }
        float* orow = out + (bh * Sc + (long)qrow) * Dc;
        ((float2*)orow)[lane] = make_float2(acc0.x + acc1.x, acc0.y + acc1.y);
    }
}

extern "C" void kernel_launch(void* const* d_in, const int* in_sizes, int n_in,
                              void* d_out, int out_size)
{
    const float* Q = (const float*)d_in[0];
    const float* K = (const float*)d_in[1];
    const float* V = (const float*)d_in[2];
    const float* R = (const float*)d_in[3];
    const int*   M = (const int*)d_in[4];

    float* out   = (float*)d_out;                    // [B,H,S,D]
    float* p_out = out + (long)Bc * Hc * Sc * Dc;    // [B,H,S,S] appended

    qk_kernel<<<dim3(64, Hc, Bc), 256>>>(Q, K);
    scores_av_kernel<<<GRIDSZ, THREADS>>>(Q, V, R, M, out, p_out);
}